// round 1
// baseline (speedup 1.0000x reference)
#include <cuda_runtime.h>
#include <math.h>

// ---------------- scratch (device globals; no allocation allowed) ----------------
__device__ float g_deltas[32768 * 128];          // [q_global][m*16 + l*8 + k*2 + comp]
__device__ float g_A[32768 * 64];                // [q_global][m*8 + s]  (softmaxed)
__device__ float g_wx0[16 * 64 * 64 * 16];       // [b*8+m][y*64+x][c]
__device__ float g_wx1[16 * 128 * 128 * 16];     // [b*8+m][y*128+x][c]
__device__ float g_pre[32768 * 128];             // [q_global][m*16 + d]

// =================================================================================
// Kernel 1: fused zq = z@Wq+bq ; deltas = zq@Wd+bd ; A = softmax(zq@Wa+ba)
// Block: 256 threads, 2 sub-tiles of 32 queries. All weights resident in smem.
// =================================================================================
__global__ void __launch_bounds__(256) k_qda(
    const float* __restrict__ z_q,
    const float* __restrict__ Wq, const float* __restrict__ bq,
    const float* __restrict__ Wd, const float* __restrict__ bd,
    const float* __restrict__ Wa, const float* __restrict__ ba)
{
    extern __shared__ float sm[];
    float* sWq = sm;                 // 16384
    float* sWd = sWq + 16384;        // 16384
    float* sWa = sWd + 16384;        // 8192
    float* sZ  = sWa + 8192;         // 4096 (z rows, later reused for A logits)
    float* sZq = sZ + 4096;          // 4096
    float* sBq = sZq + 4096;         // 128
    float* sBd = sBq + 128;          // 128
    float* sBa = sBd + 128;          // 64

    const int tid = threadIdx.x;
    {
        float4* d = (float4*)sWq; const float4* s = (const float4*)Wq;
        #pragma unroll
        for (int i = 0; i < 16; i++) d[tid + 256 * i] = s[tid + 256 * i];
        d = (float4*)sWd; s = (const float4*)Wd;
        #pragma unroll
        for (int i = 0; i < 16; i++) d[tid + 256 * i] = s[tid + 256 * i];
        d = (float4*)sWa; s = (const float4*)Wa;
        #pragma unroll
        for (int i = 0; i < 8; i++) d[tid + 256 * i] = s[tid + 256 * i];
        if (tid < 128) { sBq[tid] = bq[tid]; sBd[tid] = bd[tid]; }
        else if (tid < 192) { sBa[tid - 128] = ba[tid - 128]; }
    }

    const int qg = (tid >> 5) << 2;   // query group (4 rows)
    const int jg = (tid & 31) << 2;   // 4 output cols (128-wide)
    const int ja = (tid & 31) << 1;   // 2 output cols (64-wide)

    for (int t = 0; t < 2; t++) {
        const int q0 = (blockIdx.x * 2 + t) * 32;
        __syncthreads();   // also covers weight load on t==0, sZ reuse on t==1
        {
            float4* d = (float4*)sZ;
            const float4* s = (const float4*)(z_q + (size_t)q0 * 128);
            #pragma unroll
            for (int i = 0; i < 4; i++) d[tid + 256 * i] = s[tid + 256 * i];
        }
        __syncthreads();

        // ---- zq = z @ Wq ----
        float4 a[4];
        #pragma unroll
        for (int r = 0; r < 4; r++) a[r] = make_float4(0.f, 0.f, 0.f, 0.f);
        #pragma unroll 8
        for (int i = 0; i < 128; i++) {
            float4 w = *(const float4*)(sWq + i * 128 + jg);
            #pragma unroll
            for (int r = 0; r < 4; r++) {
                float z = sZ[(qg + r) * 128 + i];
                a[r].x = fmaf(z, w.x, a[r].x);
                a[r].y = fmaf(z, w.y, a[r].y);
                a[r].z = fmaf(z, w.z, a[r].z);
                a[r].w = fmaf(z, w.w, a[r].w);
            }
        }
        {
            float4 bv = *(const float4*)(sBq + jg);
            #pragma unroll
            for (int r = 0; r < 4; r++) {
                float4 v = a[r];
                v.x += bv.x; v.y += bv.y; v.z += bv.z; v.w += bv.w;
                *(float4*)(sZq + (qg + r) * 128 + jg) = v;
            }
        }
        __syncthreads();

        // ---- deltas = zq @ Wd + bd -> global ----
        #pragma unroll
        for (int r = 0; r < 4; r++) a[r] = make_float4(0.f, 0.f, 0.f, 0.f);
        #pragma unroll 8
        for (int i = 0; i < 128; i++) {
            float4 w = *(const float4*)(sWd + i * 128 + jg);
            #pragma unroll
            for (int r = 0; r < 4; r++) {
                float z = sZq[(qg + r) * 128 + i];
                a[r].x = fmaf(z, w.x, a[r].x);
                a[r].y = fmaf(z, w.y, a[r].y);
                a[r].z = fmaf(z, w.z, a[r].z);
                a[r].w = fmaf(z, w.w, a[r].w);
            }
        }
        {
            float4 bv = *(const float4*)(sBd + jg);
            #pragma unroll
            for (int r = 0; r < 4; r++) {
                float4 v = a[r];
                v.x += bv.x; v.y += bv.y; v.z += bv.z; v.w += bv.w;
                *(float4*)(g_deltas + (size_t)(q0 + qg + r) * 128 + jg) = v;
            }
        }

        // ---- A logits = zq @ Wa + ba -> sZ (z no longer needed) ----
        float2 aa[4];
        #pragma unroll
        for (int r = 0; r < 4; r++) aa[r] = make_float2(0.f, 0.f);
        #pragma unroll 8
        for (int i = 0; i < 128; i++) {
            float2 w = *(const float2*)(sWa + i * 64 + ja);
            #pragma unroll
            for (int r = 0; r < 4; r++) {
                float z = sZq[(qg + r) * 128 + i];
                aa[r].x = fmaf(z, w.x, aa[r].x);
                aa[r].y = fmaf(z, w.y, aa[r].y);
            }
        }
        #pragma unroll
        for (int r = 0; r < 4; r++) {
            sZ[(qg + r) * 64 + ja]     = aa[r].x + sBa[ja];
            sZ[(qg + r) * 64 + ja + 1] = aa[r].y + sBa[ja + 1];
        }
        __syncthreads();

        // ---- softmax over 8 per (q, m): one (q,m) per thread ----
        {
            const float* row = sZ + (tid >> 3) * 64 + (tid & 7) * 8;
            float mx = row[0];
            #pragma unroll
            for (int s = 1; s < 8; s++) mx = fmaxf(mx, row[s]);
            float e[8], sum = 0.f;
            #pragma unroll
            for (int s = 0; s < 8; s++) { e[s] = expf(row[s] - mx); sum += e[s]; }
            float inv = 1.f / sum;
            float* out = g_A + (size_t)(q0 + (tid >> 3)) * 64 + (tid & 7) * 8;
            #pragma unroll
            for (int s = 0; s < 8; s++) out[s] = e[s] * inv;
        }
    }
}

// =================================================================================
// Kernel 2/4: rows x 128 x 128 GEMM + bias. PERM=true writes [b,m,y,x,c] layout.
// =================================================================================
template <bool PERM>
__global__ void __launch_bounds__(256) k_gemm(
    const float* __restrict__ X, const float* __restrict__ Wt,
    const float* __restrict__ Bv, float* __restrict__ out, int hw)
{
    extern __shared__ float sm[];
    float* sW = sm;            // 16384
    float* sX = sW + 16384;    // 4096
    float* sB = sX + 4096;     // 128
    const int tid = threadIdx.x;
    {
        float4* d = (float4*)sW; const float4* s = (const float4*)Wt;
        #pragma unroll
        for (int i = 0; i < 16; i++) d[tid + 256 * i] = s[tid + 256 * i];
        if (tid < 128) sB[tid] = Bv[tid];
    }
    const int qg = (tid >> 5) << 2;
    const int jg = (tid & 31) << 2;

    for (int t = 0; t < 2; t++) {
        const int r0 = (blockIdx.x * 2 + t) * 32;
        __syncthreads();
        {
            float4* d = (float4*)sX;
            const float4* s = (const float4*)(X + (size_t)r0 * 128);
            #pragma unroll
            for (int i = 0; i < 4; i++) d[tid + 256 * i] = s[tid + 256 * i];
        }
        __syncthreads();

        float4 a[4];
        #pragma unroll
        for (int r = 0; r < 4; r++) a[r] = make_float4(0.f, 0.f, 0.f, 0.f);
        #pragma unroll 8
        for (int i = 0; i < 128; i++) {
            float4 w = *(const float4*)(sW + i * 128 + jg);
            #pragma unroll
            for (int r = 0; r < 4; r++) {
                float z = sX[(qg + r) * 128 + i];
                a[r].x = fmaf(z, w.x, a[r].x);
                a[r].y = fmaf(z, w.y, a[r].y);
                a[r].z = fmaf(z, w.z, a[r].z);
                a[r].w = fmaf(z, w.w, a[r].w);
            }
        }
        float4 bv = *(const float4*)(sB + jg);
        #pragma unroll
        for (int r = 0; r < 4; r++) {
            float4 v = a[r];
            v.x += bv.x; v.y += bv.y; v.z += bv.z; v.w += bv.w;
            int row = r0 + qg + r;
            if (PERM) {
                int b = row / hw;
                int p = row - b * hw;
                // j = m*16 + c  ->  out[((b*8+m)*hw + p)*16 + c]
                *(float4*)(out + (((size_t)(b * 8 + (jg >> 4)) * hw + p) << 4) + (jg & 15)) = v;
            } else {
                *(float4*)(out + (size_t)row * 128 + jg) = v;
            }
        }
    }
}

// =================================================================================
// Kernel 3: bilinear sampling + attention-weighted channel dot.
// Thread per (n, q', hb, l): one sample location, 16 channels, 2 outputs (d, d+1).
// Closed-form of the reference's scrambled reshape:
//   q' = ks*4096 + ws*32 + (hs>>2);  d = (hs&3)*4 + l*2 + hi;  s = c&7
//   phi batch index = (b*M+m) % B = m&1   (jnp.tile replication quirk)
// =================================================================================
__global__ void __launch_bounds__(256) k_sample(const float* __restrict__ p_q)
{
    const int t  = blockIdx.x * 256 + threadIdx.x;
    const int l  = t & 1;
    const int hb = (t >> 1) & 3;
    const int qp = (t >> 3) & 16383;
    const int n  = t >> 17;
    const int b = n >> 3, m = n & 7;
    const int ks = qp >> 12;
    const int ws = (qp >> 5) & 127;
    const int hs = ((qp & 31) << 2) + hb;

    const float4* a4 = (const float4*)(g_A + (size_t)(b * 16384 + qp) * 64 + m * 8);
    const float4 A0 = a4[0], A1 = a4[1];

    const int qs = b * 16384 + hs * 128 + ws;
    const float2 dxy = *(const float2*)(g_deltas + (size_t)qs * 128 + m * 16 + l * 8 + ks * 2);
    const float2 pq  = *(const float2*)(p_q + (size_t)((m & 1) * 16384 + hs * 128 + ws) * 2);

    const int wl = l ? 128 : 64;
    const float* img = (l ? g_wx1 : g_wx0) + (size_t)n * (wl * wl * 16);
    const float sc = (float)(wl - 1);

    const float cx = pq.x * sc + dxy.x;
    const float cy = pq.y * sc + dxy.y;
    const float gx = 2.f * cx / sc - 1.f;
    const float gy = 2.f * cy / sc - 1.f;
    const float ix = ((gx + 1.f) * (float)wl - 1.f) * 0.5f;
    const float iy = ((gy + 1.f) * (float)wl - 1.f) * 0.5f;
    const float xf = floorf(ix), yf = floorf(iy);
    const float fx1 = ix - xf, fy1 = iy - yf;
    const float fx0 = 1.f - fx1, fy0 = 1.f - fy1;
    const int x0 = (int)xf, y0 = (int)yf;

    float acc[16];
    #pragma unroll
    for (int c = 0; c < 16; c++) acc[c] = 0.f;

    #pragma unroll
    for (int tap = 0; tap < 4; tap++) {
        const int xi = x0 + (tap & 1);
        const int yi = y0 + (tap >> 1);
        const float w = ((tap & 1) ? fx1 : fx0) * ((tap >> 1) ? fy1 : fy0);
        if (xi >= 0 && xi < wl && yi >= 0 && yi < wl) {
            const float4* v4 = (const float4*)(img + ((size_t)yi * wl + xi) * 16);
            #pragma unroll
            for (int v = 0; v < 4; v++) {
                float4 vv = v4[v];
                acc[v * 4 + 0] = fmaf(w, vv.x, acc[v * 4 + 0]);
                acc[v * 4 + 1] = fmaf(w, vv.y, acc[v * 4 + 1]);
                acc[v * 4 + 2] = fmaf(w, vv.z, acc[v * 4 + 2]);
                acc[v * 4 + 3] = fmaf(w, vv.w, acc[v * 4 + 3]);
            }
        }
    }

    const float o0 = A0.x * acc[0] + A0.y * acc[1] + A0.z * acc[2] + A0.w * acc[3]
                   + A1.x * acc[4] + A1.y * acc[5] + A1.z * acc[6] + A1.w * acc[7];
    const float o1 = A0.x * acc[8]  + A0.y * acc[9]  + A0.z * acc[10] + A0.w * acc[11]
                   + A1.x * acc[12] + A1.y * acc[13] + A1.z * acc[14] + A1.w * acc[15];

    *(float2*)(g_pre + (size_t)(b * 16384 + qp) * 128 + m * 16 + hb * 4 + l * 2)
        = make_float2(o0, o1);
}

// =================================================================================
extern "C" void kernel_launch(void* const* d_in, const int* in_sizes, int n_in,
                              void* d_out, int out_size)
{
    const float* z_q = (const float*)d_in[0];
    const float* x0  = (const float*)d_in[1];
    const float* x1  = (const float*)d_in[2];
    const float* p_q = (const float*)d_in[3];
    const float* Wq  = (const float*)d_in[4];
    const float* bq  = (const float*)d_in[5];
    const float* Wd  = (const float*)d_in[6];
    const float* bd  = (const float*)d_in[7];
    const float* Wa  = (const float*)d_in[8];
    const float* ba  = (const float*)d_in[9];
    const float* Wp  = (const float*)d_in[10];
    const float* bp  = (const float*)d_in[11];
    const float* Wm  = (const float*)d_in[12];
    const float* bm  = (const float*)d_in[13];
    float* out = (float*)d_out;

    const int QDA_SMEM  = (16384 * 2 + 8192 + 4096 * 2 + 128 + 128 + 64) * 4;  // 197888
    const int GEMM_SMEM = (16384 + 4096 + 128) * 4;                            // 82432

    cudaFuncSetAttribute(k_qda, cudaFuncAttributeMaxDynamicSharedMemorySize, QDA_SMEM);
    cudaFuncSetAttribute(k_gemm<true>,  cudaFuncAttributeMaxDynamicSharedMemorySize, GEMM_SMEM);
    cudaFuncSetAttribute(k_gemm<false>, cudaFuncAttributeMaxDynamicSharedMemorySize, GEMM_SMEM);

    float *p_wx0, *p_wx1, *p_pre;
    cudaGetSymbolAddress((void**)&p_wx0, g_wx0);
    cudaGetSymbolAddress((void**)&p_wx1, g_wx1);
    cudaGetSymbolAddress((void**)&p_pre, g_pre);

    k_qda<<<512, 256, QDA_SMEM>>>(z_q, Wq, bq, Wd, bd, Wa, ba);
    k_gemm<true><<<128, 256, GEMM_SMEM>>>(x0, Wp, bp, p_wx0, 64 * 64);
    k_gemm<true><<<512, 256, GEMM_SMEM>>>(x1, Wp, bp, p_wx1, 128 * 128);
    k_sample<<<8192, 256>>>(p_q);
    k_gemm<false><<<512, 256, GEMM_SMEM>>>(p_pre, Wm, bm, out, 0);
}

// round 2
// speedup vs baseline: 1.2417x; 1.2417x over previous
#include <cuda_runtime.h>
#include <math.h>

// ---------------- scratch (device globals; no allocation allowed) ----------------
__device__ float g_deltas[32768 * 128];          // [q_global][m*16 + l*8 + k*2 + comp]
__device__ float g_A[32768 * 64];                // [q_global][m*8 + s]  (softmaxed)
__device__ float g_wx0[16 * 64 * 64 * 16];       // [b*8+m][y*64+x][c]
__device__ float g_wx1[16 * 128 * 128 * 16];     // [b*8+m][y*128+x][c]
__device__ float g_pre[32768 * 128];             // [q_global][m*16 + d]

// packed f32x2 FMA helpers (Blackwell: full-rate 2xFMA per issue slot)
__device__ __forceinline__ unsigned long long pack2(float z) {
    unsigned long long r;
    unsigned int u = __float_as_uint(z);
    asm("mov.b64 %0, {%1, %1};" : "=l"(r) : "r"(u));
    return r;
}
__device__ __forceinline__ void fma2(unsigned long long& acc, unsigned long long a,
                                     unsigned long long b) {
    asm("fma.rn.f32x2 %0, %1, %2, %3;" : "=l"(acc) : "l"(a), "l"(b), "l"(acc));
}
__device__ __forceinline__ float lo32(unsigned long long v) {
    return __uint_as_float((unsigned int)v);
}
__device__ __forceinline__ float hi32(unsigned long long v) {
    return __uint_as_float((unsigned int)(v >> 32));
}

// =================================================================================
// Kernel 1: fused zq = z@Wq+bq ; deltas = zq@Wd+bd ; A = softmax(zq@Wa+ba)
// =================================================================================
__global__ void __launch_bounds__(256) k_qda(
    const float* __restrict__ z_q,
    const float* __restrict__ Wq, const float* __restrict__ bq,
    const float* __restrict__ Wd, const float* __restrict__ bd,
    const float* __restrict__ Wa, const float* __restrict__ ba)
{
    extern __shared__ float sm[];
    float* sWq = sm;                 // 16384
    float* sWd = sWq + 16384;        // 16384
    float* sWa = sWd + 16384;        // 8192
    float* sZ  = sWa + 8192;         // 4096 (z rows, later reused for A logits)
    float* sZq = sZ + 4096;          // 4096
    float* sBq = sZq + 4096;         // 128
    float* sBd = sBq + 128;          // 128
    float* sBa = sBd + 128;          // 64

    const int tid = threadIdx.x;
    {
        float4* d = (float4*)sWq; const float4* s = (const float4*)Wq;
        #pragma unroll
        for (int i = 0; i < 16; i++) d[tid + 256 * i] = s[tid + 256 * i];
        d = (float4*)sWd; s = (const float4*)Wd;
        #pragma unroll
        for (int i = 0; i < 16; i++) d[tid + 256 * i] = s[tid + 256 * i];
        d = (float4*)sWa; s = (const float4*)Wa;
        #pragma unroll
        for (int i = 0; i < 8; i++) d[tid + 256 * i] = s[tid + 256 * i];
        if (tid < 128) { sBq[tid] = bq[tid]; sBd[tid] = bd[tid]; }
        else if (tid < 192) { sBa[tid - 128] = ba[tid - 128]; }
    }

    const int qg = (tid >> 5) << 2;   // query group (4 rows)
    const int jg = (tid & 31) << 2;   // 4 output cols (128-wide)
    const int ja = (tid & 31) << 1;   // 2 output cols (64-wide)

    for (int t = 0; t < 2; t++) {
        const int q0 = (blockIdx.x * 2 + t) * 32;
        __syncthreads();
        {
            float4* d = (float4*)sZ;
            const float4* s = (const float4*)(z_q + (size_t)q0 * 128);
            #pragma unroll
            for (int i = 0; i < 4; i++) d[tid + 256 * i] = s[tid + 256 * i];
        }
        __syncthreads();

        // ---- zq = z @ Wq + bq -> sZq ----
        {
            unsigned long long acc[4][2] = {};
            #pragma unroll 8
            for (int i = 0; i < 128; i++) {
                ulonglong2 w = *(const ulonglong2*)(sWq + i * 128 + jg);
                #pragma unroll
                for (int r = 0; r < 4; r++) {
                    unsigned long long zz = pack2(sZ[(qg + r) * 128 + i]);
                    fma2(acc[r][0], zz, w.x);
                    fma2(acc[r][1], zz, w.y);
                }
            }
            float4 bv = *(const float4*)(sBq + jg);
            #pragma unroll
            for (int r = 0; r < 4; r++) {
                float4 v = make_float4(lo32(acc[r][0]) + bv.x, hi32(acc[r][0]) + bv.y,
                                       lo32(acc[r][1]) + bv.z, hi32(acc[r][1]) + bv.w);
                *(float4*)(sZq + (qg + r) * 128 + jg) = v;
            }
        }
        __syncthreads();

        // ---- deltas = zq @ Wd + bd -> global ----
        {
            unsigned long long acc[4][2] = {};
            #pragma unroll 8
            for (int i = 0; i < 128; i++) {
                ulonglong2 w = *(const ulonglong2*)(sWd + i * 128 + jg);
                #pragma unroll
                for (int r = 0; r < 4; r++) {
                    unsigned long long zz = pack2(sZq[(qg + r) * 128 + i]);
                    fma2(acc[r][0], zz, w.x);
                    fma2(acc[r][1], zz, w.y);
                }
            }
            float4 bv = *(const float4*)(sBd + jg);
            #pragma unroll
            for (int r = 0; r < 4; r++) {
                float4 v = make_float4(lo32(acc[r][0]) + bv.x, hi32(acc[r][0]) + bv.y,
                                       lo32(acc[r][1]) + bv.z, hi32(acc[r][1]) + bv.w);
                *(float4*)(g_deltas + (size_t)(q0 + qg + r) * 128 + jg) = v;
            }
        }

        // ---- A logits = zq @ Wa + ba -> sZ (z no longer needed) ----
        {
            unsigned long long acc[4] = {};
            #pragma unroll 8
            for (int i = 0; i < 128; i++) {
                unsigned long long w = *(const unsigned long long*)(sWa + i * 64 + ja);
                #pragma unroll
                for (int r = 0; r < 4; r++) {
                    unsigned long long zz = pack2(sZq[(qg + r) * 128 + i]);
                    fma2(acc[r], zz, w);
                }
            }
            #pragma unroll
            for (int r = 0; r < 4; r++) {
                sZ[(qg + r) * 64 + ja]     = lo32(acc[r]) + sBa[ja];
                sZ[(qg + r) * 64 + ja + 1] = hi32(acc[r]) + sBa[ja + 1];
            }
        }
        __syncthreads();

        // ---- softmax over 8 per (q, m) ----
        {
            const float* row = sZ + (tid >> 3) * 64 + (tid & 7) * 8;
            float mx = row[0];
            #pragma unroll
            for (int s = 1; s < 8; s++) mx = fmaxf(mx, row[s]);
            float e[8], sum = 0.f;
            #pragma unroll
            for (int s = 0; s < 8; s++) { e[s] = expf(row[s] - mx); sum += e[s]; }
            float inv = 1.f / sum;
            float* out = g_A + (size_t)(q0 + (tid >> 3)) * 64 + (tid & 7) * 8;
            #pragma unroll
            for (int s = 0; s < 8; s++) out[s] = e[s] * inv;
        }
    }
}

// =================================================================================
// Kernel 2/4: rows x 128 x 128 GEMM + bias. PERM=true writes [b,m,y,x,c] layout.
// =================================================================================
template <bool PERM>
__global__ void __launch_bounds__(256) k_gemm(
    const float* __restrict__ X, const float* __restrict__ Wt,
    const float* __restrict__ Bv, float* __restrict__ out, int hw)
{
    extern __shared__ float sm[];
    float* sW = sm;            // 16384
    float* sX = sW + 16384;    // 4096
    float* sB = sX + 4096;     // 128
    const int tid = threadIdx.x;
    {
        float4* d = (float4*)sW; const float4* s = (const float4*)Wt;
        #pragma unroll
        for (int i = 0; i < 16; i++) d[tid + 256 * i] = s[tid + 256 * i];
        if (tid < 128) sB[tid] = Bv[tid];
    }
    const int qg = (tid >> 5) << 2;
    const int jg = (tid & 31) << 2;

    for (int t = 0; t < 2; t++) {
        const int r0 = (blockIdx.x * 2 + t) * 32;
        __syncthreads();
        {
            float4* d = (float4*)sX;
            const float4* s = (const float4*)(X + (size_t)r0 * 128);
            #pragma unroll
            for (int i = 0; i < 4; i++) d[tid + 256 * i] = s[tid + 256 * i];
        }
        __syncthreads();

        unsigned long long acc[4][2] = {};
        #pragma unroll 8
        for (int i = 0; i < 128; i++) {
            ulonglong2 w = *(const ulonglong2*)(sW + i * 128 + jg);
            #pragma unroll
            for (int r = 0; r < 4; r++) {
                unsigned long long zz = pack2(sX[(qg + r) * 128 + i]);
                fma2(acc[r][0], zz, w.x);
                fma2(acc[r][1], zz, w.y);
            }
        }
        float4 bv = *(const float4*)(sB + jg);
        #pragma unroll
        for (int r = 0; r < 4; r++) {
            float4 v = make_float4(lo32(acc[r][0]) + bv.x, hi32(acc[r][0]) + bv.y,
                                   lo32(acc[r][1]) + bv.z, hi32(acc[r][1]) + bv.w);
            int row = r0 + qg + r;
            if (PERM) {
                int b = row / hw;
                int p = row - b * hw;
                *(float4*)(out + (((size_t)(b * 8 + (jg >> 4)) * hw + p) << 4) + (jg & 15)) = v;
            } else {
                *(float4*)(out + (size_t)row * 128 + jg) = v;
            }
        }
    }
}

// =================================================================================
// Kernel 3: bilinear sampling + attention-weighted channel dot.
// 4 lanes cooperate per sample location (lane = channel quarter): each tap's 64B
// is fetched by 4 consecutive lanes within one 128B line -> coalesced L1 access.
// Cross-lane reduction via shfl_xor; lane 0 writes the (d, d+1) float2.
//   q' = ks*4096 + ws*32 + (hs>>2);  d = (hs&3)*4 + l*2 + hi
//   phi batch index = (b*M+m) % B = m&1   (jnp.tile replication quirk)
// =================================================================================
__global__ void __launch_bounds__(256) k_sample(const float* __restrict__ p_q)
{
    const int t    = blockIdx.x * 256 + threadIdx.x;
    const int lane = t & 3;          // channel quarter: channels lane*4 .. lane*4+3
    const int loc  = t >> 2;
    const int l  = loc & 1;
    const int hb = (loc >> 1) & 3;
    const int qp = (loc >> 3) & 16383;
    const int n  = loc >> 17;
    const int b = n >> 3, m = n & 7;
    const int ks = qp >> 12;
    const int ws = (qp >> 5) & 127;
    const int hs = ((qp & 31) << 2) + hb;

    // attention weights for this lane's 4 channels: s = c & 7
    const float4 Aw = *(const float4*)(g_A + (size_t)(b * 16384 + qp) * 64 + m * 8
                                       + ((lane & 1) << 2));

    const int qs = b * 16384 + hs * 128 + ws;
    const float2 dxy = *(const float2*)(g_deltas + (size_t)qs * 128 + m * 16 + l * 8 + ks * 2);
    const float2 pq  = *(const float2*)(p_q + (size_t)((m & 1) * 16384 + hs * 128 + ws) * 2);

    const int wl = l ? 128 : 64;
    const float* img = (l ? g_wx1 : g_wx0) + (size_t)n * (wl * wl * 16) + lane * 4;
    const float sc = (float)(wl - 1);

    const float cx = pq.x * sc + dxy.x;
    const float cy = pq.y * sc + dxy.y;
    const float gx = 2.f * cx / sc - 1.f;
    const float gy = 2.f * cy / sc - 1.f;
    const float ix = ((gx + 1.f) * (float)wl - 1.f) * 0.5f;
    const float iy = ((gy + 1.f) * (float)wl - 1.f) * 0.5f;
    const float xf = floorf(ix), yf = floorf(iy);
    const float fx1 = ix - xf, fy1 = iy - yf;
    const float fx0 = 1.f - fx1, fy0 = 1.f - fy1;
    const int x0 = (int)xf, y0 = (int)yf;

    float acc0 = 0.f, acc1 = 0.f, acc2 = 0.f, acc3 = 0.f;
    #pragma unroll
    for (int tap = 0; tap < 4; tap++) {
        const int xi = x0 + (tap & 1);
        const int yi = y0 + (tap >> 1);
        const float w = ((tap & 1) ? fx1 : fx0) * ((tap >> 1) ? fy1 : fy0);
        if (xi >= 0 && xi < wl && yi >= 0 && yi < wl) {
            float4 v = *(const float4*)(img + (((size_t)yi * wl + xi) << 4));
            acc0 = fmaf(w, v.x, acc0);
            acc1 = fmaf(w, v.y, acc1);
            acc2 = fmaf(w, v.z, acc2);
            acc3 = fmaf(w, v.w, acc3);
        }
    }

    // partial channel-dot for this lane's 4 channels
    float p = Aw.x * acc0 + Aw.y * acc1 + Aw.z * acc2 + Aw.w * acc3;
    // lanes {0,1} -> o0 (channels 0-7); lanes {2,3} -> o1 (channels 8-15)
    float s1 = p + __shfl_xor_sync(0xffffffffu, p, 1);
    float s2 = __shfl_xor_sync(0xffffffffu, s1, 2);
    if (lane == 0) {
        *(float2*)(g_pre + (size_t)(b * 16384 + qp) * 128 + m * 16 + hb * 4 + l * 2)
            = make_float2(s1, s2);
    }
}

// =================================================================================
extern "C" void kernel_launch(void* const* d_in, const int* in_sizes, int n_in,
                              void* d_out, int out_size)
{
    const float* z_q = (const float*)d_in[0];
    const float* x0  = (const float*)d_in[1];
    const float* x1  = (const float*)d_in[2];
    const float* p_q = (const float*)d_in[3];
    const float* Wq  = (const float*)d_in[4];
    const float* bq  = (const float*)d_in[5];
    const float* Wd  = (const float*)d_in[6];
    const float* bd  = (const float*)d_in[7];
    const float* Wa  = (const float*)d_in[8];
    const float* ba  = (const float*)d_in[9];
    const float* Wp  = (const float*)d_in[10];
    const float* bp  = (const float*)d_in[11];
    const float* Wm  = (const float*)d_in[12];
    const float* bm  = (const float*)d_in[13];
    float* out = (float*)d_out;

    const int QDA_SMEM  = (16384 * 2 + 8192 + 4096 * 2 + 128 + 128 + 64) * 4;  // 197888
    const int GEMM_SMEM = (16384 + 4096 + 128) * 4;                            // 82432

    cudaFuncSetAttribute(k_qda, cudaFuncAttributeMaxDynamicSharedMemorySize, QDA_SMEM);
    cudaFuncSetAttribute(k_gemm<true>,  cudaFuncAttributeMaxDynamicSharedMemorySize, GEMM_SMEM);
    cudaFuncSetAttribute(k_gemm<false>, cudaFuncAttributeMaxDynamicSharedMemorySize, GEMM_SMEM);

    float *p_wx0, *p_wx1, *p_pre;
    cudaGetSymbolAddress((void**)&p_wx0, g_wx0);
    cudaGetSymbolAddress((void**)&p_wx1, g_wx1);
    cudaGetSymbolAddress((void**)&p_pre, g_pre);

    k_qda<<<512, 256, QDA_SMEM>>>(z_q, Wq, bq, Wd, bd, Wa, ba);
    k_gemm<true><<<128, 256, GEMM_SMEM>>>(x0, Wp, bp, p_wx0, 64 * 64);
    k_gemm<true><<<512, 256, GEMM_SMEM>>>(x1, Wp, bp, p_wx1, 128 * 128);
    k_sample<<<32768, 256>>>(p_q);
    k_gemm<false><<<512, 256, GEMM_SMEM>>>(p_pre, Wm, bm, out, 0);
}

// round 3
// speedup vs baseline: 1.4656x; 1.1803x over previous
#include <cuda_runtime.h>
#include <math.h>

// ---------------- scratch (device globals; no allocation allowed) ----------------
__device__ float g_zq[32768 * 128];              // zq = z@Wq + bq
__device__ float g_deltas[32768 * 128];          // [q][m*16 + l*8 + k*2 + comp]
__device__ float g_A[32768 * 64];                // [q][m*8 + s]  (softmaxed)
__device__ float g_wx0[16 * 64 * 64 * 16];       // [b*8+m][y*64+x][c]
__device__ float g_wx1[16 * 128 * 128 * 16];     // [b*8+m][y*128+x][c]
__device__ float g_pre[32768 * 128];             // [q'][m*16 + d]

// packed f32x2 FMA helpers
__device__ __forceinline__ unsigned long long pack2(float z) {
    unsigned long long r;
    unsigned int u = __float_as_uint(z);
    asm("mov.b64 %0, {%1, %1};" : "=l"(r) : "r"(u));
    return r;
}
__device__ __forceinline__ void fma2(unsigned long long& acc, unsigned long long a,
                                     unsigned long long b) {
    asm("fma.rn.f32x2 %0, %1, %2, %3;" : "=l"(acc) : "l"(a), "l"(b), "l"(acc));
}
__device__ __forceinline__ float lo32(unsigned long long v) {
    return __uint_as_float((unsigned int)v);
}
__device__ __forceinline__ float hi32(unsigned long long v) {
    return __uint_as_float((unsigned int)(v >> 32));
}

// =================================================================================
// Generic GEMM: out[ROWS x 128] = X[ROWS x 128] @ Wt[128 x 128] + Bv.
// Block = ROWS*2 threads; per-thread 8x8 register tile; K=128 smem-resident.
// LDS traffic = 1 B/MAC -> FFMA2-pipe bound. PERM writes the [b,m,y,x,c] layout.
// =================================================================================
template <int ROWS, bool PERM>
__global__ void __launch_bounds__(ROWS * 2) k_gemm(
    const float* __restrict__ X, const float* __restrict__ Wt,
    const float* __restrict__ Bv, float* __restrict__ out, int hwshift)
{
    constexpr int THREADS = ROWS * 2;
    extern __shared__ float sm[];
    float* sX = sm;                 // ROWS*128
    float* sW = sX + ROWS * 128;    // 16384
    float* sB = sW + 16384;         // 128

    const int tid = threadIdx.x;
    const int r0 = blockIdx.x * ROWS;
    {
        float4* d = (float4*)sX;
        const float4* s = (const float4*)(X + (size_t)r0 * 128);
        #pragma unroll
        for (int j = 0; j < ROWS * 32 / THREADS; j++) d[tid + THREADS * j] = s[tid + THREADS * j];
        d = (float4*)sW; s = (const float4*)Wt;
        #pragma unroll
        for (int j = 0; j < 4096 / THREADS; j++) d[tid + THREADS * j] = s[tid + THREADS * j];
        if (tid < 128) sB[tid] = Bv[tid];
    }
    __syncthreads();

    const int ty = tid >> 4;          // ROWS/8 row-groups of 8
    const int tx = tid & 15;          // 16 col-groups of 8
    const float* xrow = sX + ty * 8 * 128;
    const float* wcol = sW + tx * 8;

    unsigned long long acc[8][4] = {};
    #pragma unroll 2
    for (int k = 0; k < 128; k += 2) {
        float2 zv[8];
        #pragma unroll
        for (int r = 0; r < 8; r++) zv[r] = *(const float2*)(xrow + r * 128 + k);
        #pragma unroll
        for (int kk = 0; kk < 2; kk++) {
            ulonglong2 wa = *(const ulonglong2*)(wcol + (k + kk) * 128);
            ulonglong2 wb = *(const ulonglong2*)(wcol + (k + kk) * 128 + 4);
            #pragma unroll
            for (int r = 0; r < 8; r++) {
                unsigned long long zz = pack2(kk ? zv[r].y : zv[r].x);
                fma2(acc[r][0], zz, wa.x);
                fma2(acc[r][1], zz, wa.y);
                fma2(acc[r][2], zz, wb.x);
                fma2(acc[r][3], zz, wb.y);
            }
        }
    }

    const float4 bv0 = *(const float4*)(sB + tx * 8);
    const float4 bv1 = *(const float4*)(sB + tx * 8 + 4);
    #pragma unroll
    for (int r = 0; r < 8; r++) {
        float4 v0 = make_float4(lo32(acc[r][0]) + bv0.x, hi32(acc[r][0]) + bv0.y,
                                lo32(acc[r][1]) + bv0.z, hi32(acc[r][1]) + bv0.w);
        float4 v1 = make_float4(lo32(acc[r][2]) + bv1.x, hi32(acc[r][2]) + bv1.y,
                                lo32(acc[r][3]) + bv1.z, hi32(acc[r][3]) + bv1.w);
        const int row = r0 + ty * 8 + r;
        if (PERM) {
            const int b = row >> hwshift;
            const int p = row & ((1 << hwshift) - 1);
            const int m = tx >> 1;
            const int cb = (tx & 1) * 8;
            float* o = out + ((((size_t)(b * 8 + m) << hwshift) + p) << 4) + cb;
            *(float4*)o = v0;
            *(float4*)(o + 4) = v1;
        } else {
            float* o = out + (size_t)row * 128 + tx * 8;
            *(float4*)o = v0;
            *(float4*)(o + 4) = v1;
        }
    }
}

// =================================================================================
// A GEMM (N=64) with fused softmax: A = softmax(zq @ Wa + ba) over groups of 8.
// Block 512 threads, 256 rows; per-thread 4 rows x 8 cols (= one full m-group).
// =================================================================================
__global__ void __launch_bounds__(512) k_gemmA(
    const float* __restrict__ X, const float* __restrict__ Wa,
    const float* __restrict__ ba)
{
    extern __shared__ float sm[];
    float* sX = sm;                 // 256*128
    float* sW = sX + 32768;         // 8192
    float* sB = sW + 8192;          // 64

    const int tid = threadIdx.x;
    const int r0 = blockIdx.x * 256;
    {
        float4* d = (float4*)sX;
        const float4* s = (const float4*)(X + (size_t)r0 * 128);
        #pragma unroll
        for (int j = 0; j < 16; j++) d[tid + 512 * j] = s[tid + 512 * j];
        d = (float4*)sW; s = (const float4*)Wa;
        #pragma unroll
        for (int j = 0; j < 4; j++) d[tid + 512 * j] = s[tid + 512 * j];
        if (tid < 64) sB[tid] = ba[tid];
    }
    __syncthreads();

    const int ty = tid >> 3;          // 64 row-groups of 4
    const int tx = tid & 7;           // 8 col-groups of 8 (= m)
    const float* xrow = sX + ty * 4 * 128;
    const float* wcol = sW + tx * 8;

    unsigned long long acc[4][4] = {};
    #pragma unroll 2
    for (int k = 0; k < 128; k += 2) {
        float2 zv[4];
        #pragma unroll
        for (int r = 0; r < 4; r++) zv[r] = *(const float2*)(xrow + r * 128 + k);
        #pragma unroll
        for (int kk = 0; kk < 2; kk++) {
            ulonglong2 wa = *(const ulonglong2*)(wcol + (k + kk) * 64);
            ulonglong2 wb = *(const ulonglong2*)(wcol + (k + kk) * 64 + 4);
            #pragma unroll
            for (int r = 0; r < 4; r++) {
                unsigned long long zz = pack2(kk ? zv[r].y : zv[r].x);
                fma2(acc[r][0], zz, wa.x);
                fma2(acc[r][1], zz, wa.y);
                fma2(acc[r][2], zz, wb.x);
                fma2(acc[r][3], zz, wb.y);
            }
        }
    }

    float b0 = sB[tx * 8], b1 = sB[tx * 8 + 1], b2 = sB[tx * 8 + 2], b3 = sB[tx * 8 + 3];
    float b4 = sB[tx * 8 + 4], b5 = sB[tx * 8 + 5], b6 = sB[tx * 8 + 6], b7 = sB[tx * 8 + 7];
    #pragma unroll
    for (int r = 0; r < 4; r++) {
        float e[8];
        e[0] = lo32(acc[r][0]) + b0; e[1] = hi32(acc[r][0]) + b1;
        e[2] = lo32(acc[r][1]) + b2; e[3] = hi32(acc[r][1]) + b3;
        e[4] = lo32(acc[r][2]) + b4; e[5] = hi32(acc[r][2]) + b5;
        e[6] = lo32(acc[r][3]) + b6; e[7] = hi32(acc[r][3]) + b7;
        float mx = e[0];
        #pragma unroll
        for (int s = 1; s < 8; s++) mx = fmaxf(mx, e[s]);
        float sum = 0.f;
        #pragma unroll
        for (int s = 0; s < 8; s++) { e[s] = expf(e[s] - mx); sum += e[s]; }
        float inv = 1.f / sum;
        float* o = g_A + (size_t)(r0 + ty * 4 + r) * 64 + tx * 8;
        *(float4*)o       = make_float4(e[0] * inv, e[1] * inv, e[2] * inv, e[3] * inv);
        *(float4*)(o + 4) = make_float4(e[4] * inv, e[5] * inv, e[6] * inv, e[7] * inv);
    }
}

// =================================================================================
// Sampler: 4 lanes per location (lane = channel quarter), BOTH levels per thread.
// All-int32 addressing, fused coordinate math, one float4 output per location.
// =================================================================================
__global__ void __launch_bounds__(256) k_sample(const float* __restrict__ p_q)
{
    const int t    = blockIdx.x * 256 + threadIdx.x;
    const int lane = t & 3;
    const int loc  = t >> 2;
    const int hb = loc & 3;
    const int qp = (loc >> 2) & 16383;
    const int n  = loc >> 16;
    const int b = n >> 3, m = n & 7;
    const int ks = qp >> 12;
    const int ws = (qp >> 5) & 127;
    const int hs = ((qp & 31) << 2) + hb;

    const float4 Aw = *(const float4*)(g_A + (b * 16384 + qp) * 64 + m * 8 + ((lane & 1) << 2));

    const float* dptr = g_deltas + (b * 16384 + hs * 128 + ws) * 128 + m * 16 + ks * 2;
    const float2 d0 = *(const float2*)dptr;
    const float2 d1 = *(const float2*)(dptr + 8);
    const float2 pq = *(const float2*)(p_q + ((m & 1) * 16384 + hs * 128 + ws) * 2);

    float res[4];
    #pragma unroll
    for (int l = 0; l < 2; l++) {
        const int wl = l ? 128 : 64;
        const float sc = l ? 127.f : 63.f;
        const float mult = (float)wl / sc;
        const float* img = (l ? g_wx1 : g_wx0) + n * (wl * wl * 16) + lane * 4;
        const float2 dxy = l ? d1 : d0;

        const float ix = fmaf(fmaf(pq.x, sc, dxy.x), mult, -0.5f);
        const float iy = fmaf(fmaf(pq.y, sc, dxy.y), mult, -0.5f);
        const float xf = floorf(ix), yf = floorf(iy);
        const float fx1 = ix - xf, fy1 = iy - yf;
        const float fx0 = 1.f - fx1, fy0 = 1.f - fy1;
        const int x0 = (int)xf, y0 = (int)yf;

        float a0 = 0.f, a1 = 0.f, a2 = 0.f, a3 = 0.f;
        #pragma unroll
        for (int tap = 0; tap < 4; tap++) {
            const int xi = x0 + (tap & 1);
            const int yi = y0 + (tap >> 1);
            const float w = ((tap & 1) ? fx1 : fx0) * ((tap >> 1) ? fy1 : fy0);
            if (xi >= 0 && xi < wl && yi >= 0 && yi < wl) {
                float4 v = *(const float4*)(img + ((yi * wl + xi) << 4));
                a0 = fmaf(w, v.x, a0);
                a1 = fmaf(w, v.y, a1);
                a2 = fmaf(w, v.z, a2);
                a3 = fmaf(w, v.w, a3);
            }
        }
        float p = Aw.x * a0 + Aw.y * a1 + Aw.z * a2 + Aw.w * a3;
        float s1 = p + __shfl_xor_sync(0xffffffffu, p, 1);
        float s2 = __shfl_xor_sync(0xffffffffu, s1, 2);
        res[l * 2]     = s1;
        res[l * 2 + 1] = s2;
    }
    if (lane == 0) {
        *(float4*)(g_pre + (size_t)(b * 16384 + qp) * 128 + m * 16 + hb * 4)
            = make_float4(res[0], res[1], res[2], res[3]);
    }
}

// =================================================================================
extern "C" void kernel_launch(void* const* d_in, const int* in_sizes, int n_in,
                              void* d_out, int out_size)
{
    const float* z_q = (const float*)d_in[0];
    const float* x0  = (const float*)d_in[1];
    const float* x1  = (const float*)d_in[2];
    const float* p_q = (const float*)d_in[3];
    const float* Wq  = (const float*)d_in[4];
    const float* bq  = (const float*)d_in[5];
    const float* Wd  = (const float*)d_in[6];
    const float* bd  = (const float*)d_in[7];
    const float* Wa  = (const float*)d_in[8];
    const float* ba  = (const float*)d_in[9];
    const float* Wp  = (const float*)d_in[10];
    const float* bp  = (const float*)d_in[11];
    const float* Wm  = (const float*)d_in[12];
    const float* bm  = (const float*)d_in[13];
    float* out = (float*)d_out;

    const int G256 = (256 * 128 + 16384 + 128) * 4;   // 197120
    const int G64  = (64 * 128 + 16384 + 128) * 4;    // 98816
    const int GA   = (256 * 128 + 8192 + 64) * 4;     // 164096

    cudaFuncSetAttribute(k_gemm<256, false>, cudaFuncAttributeMaxDynamicSharedMemorySize, G256);
    cudaFuncSetAttribute(k_gemm<256, true>,  cudaFuncAttributeMaxDynamicSharedMemorySize, G256);
    cudaFuncSetAttribute(k_gemm<64, true>,   cudaFuncAttributeMaxDynamicSharedMemorySize, G64);
    cudaFuncSetAttribute(k_gemmA,            cudaFuncAttributeMaxDynamicSharedMemorySize, GA);

    float *p_zq, *p_deltas, *p_wx0, *p_wx1, *p_pre;
    cudaGetSymbolAddress((void**)&p_zq, g_zq);
    cudaGetSymbolAddress((void**)&p_deltas, g_deltas);
    cudaGetSymbolAddress((void**)&p_wx0, g_wx0);
    cudaGetSymbolAddress((void**)&p_wx1, g_wx1);
    cudaGetSymbolAddress((void**)&p_pre, g_pre);

    // zq = z @ Wq + bq
    k_gemm<256, false><<<128, 512, G256>>>(z_q, Wq, bq, p_zq, 0);
    // deltas = zq @ Wd + bd
    k_gemm<256, false><<<128, 512, G256>>>(p_zq, Wd, bd, p_deltas, 0);
    // A = softmax(zq @ Wa + ba)
    k_gemmA<<<128, 512, GA>>>(p_zq, Wa, ba);
    // Wx projections (permuted layout)
    k_gemm<64, true><<<128, 128, G64>>>(x0, Wp, bp, p_wx0, 12);
    k_gemm<256, true><<<128, 512, G256>>>(x1, Wp, bp, p_wx1, 14);
    // sampling + attention dot
    k_sample<<<16384, 256>>>(p_q);
    // out = pre @ Wm + bm
    k_gemm<256, false><<<128, 512, G256>>>(p_pre, Wm, bm, out, 0);
}

// round 5
// speedup vs baseline: 1.7705x; 1.2081x over previous
#include <cuda_runtime.h>
#include <cuda_bf16.h>
#include <math.h>
#include <stdint.h>

// ---------------- scratch (device globals; no allocation allowed) ----------------
__device__ float g_deltas[32768 * 128];          // [q][m*16 + l*8 + k*2 + comp]
__device__ float g_A[32768 * 64];                // [q][m*8 + s]  (softmaxed)
__device__ float g_wx0[16 * 64 * 64 * 16];       // [b*8+m][y*64+x][c]
__device__ float g_wx1[16 * 128 * 128 * 16];     // [b*8+m][y*128+x][c]
__device__ float g_pre[32768 * 128];             // [q'][m*16 + d]
__device__ __nv_bfloat16 g_zq_hi[32768 * 128];   // zq split, [row][k]
__device__ __nv_bfloat16 g_zq_lo[32768 * 128];

// weights pre-split to bf16 hi/lo, stored transposed [n][k] (B col-major for mma)
__device__ __nv_bfloat16 g_Wq_hi[16384], g_Wq_lo[16384];
__device__ __nv_bfloat16 g_Wd_hi[16384], g_Wd_lo[16384];
__device__ __nv_bfloat16 g_Wp_hi[16384], g_Wp_lo[16384];
__device__ __nv_bfloat16 g_Wm_hi[16384], g_Wm_lo[16384];
__device__ __nv_bfloat16 g_Wa_hi[8192],  g_Wa_lo[8192];

// ---------------- helpers ----------------
__device__ __forceinline__ uint32_t smem_u32(const void* p) {
    uint32_t a;
    asm("{ .reg .u64 t; cvta.to.shared.u64 t, %1; cvt.u32.u64 %0, t; }" : "=r"(a) : "l"(p));
    return a;
}
__device__ __forceinline__ void ldm_x4(uint32_t* r, uint32_t addr) {
    asm volatile("ldmatrix.sync.aligned.m8n8.x4.shared.b16 {%0,%1,%2,%3}, [%4];"
        : "=r"(r[0]), "=r"(r[1]), "=r"(r[2]), "=r"(r[3]) : "r"(addr));
}
__device__ __forceinline__ void mma_bf16(float* d, const uint32_t* a, const uint32_t* b) {
    asm volatile("mma.sync.aligned.m16n8k16.row.col.f32.bf16.bf16.f32 "
        "{%0,%1,%2,%3}, {%4,%5,%6,%7}, {%8,%9}, {%0,%1,%2,%3};"
        : "+f"(d[0]), "+f"(d[1]), "+f"(d[2]), "+f"(d[3])
        : "r"(a[0]), "r"(a[1]), "r"(a[2]), "r"(a[3]), "r"(b[0]), "r"(b[1]));
}
// fp32 pair -> packed bf16 hi pair + bf16 residual pair
__device__ __forceinline__ void cvt2(float f0, float f1, uint32_t& hi, uint32_t& lo) {
    __nv_bfloat162 h2 = __floats2bfloat162_rn(f0, f1);
    float2 hb = __bfloat1622float2(h2);
    __nv_bfloat162 l2 = __floats2bfloat162_rn(f0 - hb.x, f1 - hb.y);
    hi = *reinterpret_cast<uint32_t*>(&h2);
    lo = *reinterpret_cast<uint32_t*>(&l2);
}

// =================================================================================
// Weight prep: W row-major [K=128][N] -> transposed [n][k] bf16 hi/lo planes
// =================================================================================
__global__ void __launch_bounds__(256) k_prep(
    const float* __restrict__ Wq, const float* __restrict__ Wd,
    const float* __restrict__ Wa, const float* __restrict__ Wp,
    const float* __restrict__ Wm)
{
    const int i = blockIdx.x * 256 + threadIdx.x;
    const float* src;
    __nv_bfloat16 *dhi, *dlo;
    int N, idx;
    if      (i < 16384) { src = Wq; dhi = g_Wq_hi; dlo = g_Wq_lo; N = 128; idx = i; }
    else if (i < 32768) { src = Wd; dhi = g_Wd_hi; dlo = g_Wd_lo; N = 128; idx = i - 16384; }
    else if (i < 49152) { src = Wp; dhi = g_Wp_hi; dlo = g_Wp_lo; N = 128; idx = i - 32768; }
    else if (i < 65536) { src = Wm; dhi = g_Wm_hi; dlo = g_Wm_lo; N = 128; idx = i - 49152; }
    else if (i < 73728) { src = Wa; dhi = g_Wa_hi; dlo = g_Wa_lo; N = 64;  idx = i - 65536; }
    else return;
    const int n = idx >> 7, k = idx & 127;
    const float w = src[k * N + n];
    const __nv_bfloat16 h = __float2bfloat16(w);
    const __nv_bfloat16 l = __float2bfloat16(w - __bfloat162float(h));
    dhi[idx] = h;
    dlo[idx] = l;
}

// =================================================================================
// HMMA GEMM: out[256 x N] = X[256 x 128] @ W^T + bias, 3-term bf16 split.
// 512 threads = 16 warps: warp w -> m block (w&7)*32, n block (w>>3)*(N/2).
// INB: X given as bf16 hi/lo planes.  OMODE: 0 fp32, 1 bf16 hi/lo, 2 perm, 3 softmax.
// smem rows padded to 136 bf16 (272 B) for conflict-free ldmatrix.
// =================================================================================
template <int N, int INB, int OMODE>
__global__ void __launch_bounds__(512) k_mma(
    const float* __restrict__ Xf,
    const __nv_bfloat16* __restrict__ Xh, const __nv_bfloat16* __restrict__ Xl,
    const __nv_bfloat16* __restrict__ Bh, const __nv_bfloat16* __restrict__ Bl,
    const float* __restrict__ bias, float* __restrict__ outf,
    __nv_bfloat16* __restrict__ outh, __nv_bfloat16* __restrict__ outl,
    int hwshift)
{
    extern __shared__ char smem[];
    constexpr int HI_A = 0;
    constexpr int LO_A = 256 * 272;              // 69632
    constexpr int HI_B = 2 * 256 * 272;          // 139264
    constexpr int LO_B = HI_B + N * 272;
    float* sBias = (float*)(smem + HI_B + 2 * N * 272);

    const int tid = threadIdx.x;
    const int r0 = blockIdx.x * 256;

    if (INB) {
        const uint4* sh = (const uint4*)(Xh + (size_t)r0 * 128);
        const uint4* sl = (const uint4*)(Xl + (size_t)r0 * 128);
        #pragma unroll
        for (int it = 0; it < 8; it++) {
            const int idx = it * 512 + tid;
            const int row = idx >> 4, seg = idx & 15;
            *(uint4*)(smem + HI_A + row * 272 + seg * 16) = sh[idx];
            *(uint4*)(smem + LO_A + row * 272 + seg * 16) = sl[idx];
        }
    } else {
        #pragma unroll
        for (int it = 0; it < 16; it++) {
            const int idx = it * 512 + tid;
            const int row = idx >> 5, c4 = (idx & 31) << 2;
            const float4 f = *(const float4*)(Xf + (size_t)r0 * 128 + row * 128 + c4);
            uint32_t h0, l0, h1, l1;
            cvt2(f.x, f.y, h0, l0);
            cvt2(f.z, f.w, h1, l1);
            *(uint2*)(smem + HI_A + row * 272 + c4 * 2) = make_uint2(h0, h1);
            *(uint2*)(smem + LO_A + row * 272 + c4 * 2) = make_uint2(l0, l1);
        }
    }
    {
        const uint4* sh = (const uint4*)Bh;
        const uint4* sl = (const uint4*)Bl;
        #pragma unroll
        for (int it = 0; it < N * 16 / 512; it++) {
            const int idx = it * 512 + tid;
            const int row = idx >> 4, seg = idx & 15;
            *(uint4*)(smem + HI_B + row * 272 + seg * 16) = sh[idx];
            *(uint4*)(smem + LO_B + row * 272 + seg * 16) = sl[idx];
        }
        if (tid < N) sBias[tid] = bias[tid];
    }
    __syncthreads();

    const uint32_t sb = smem_u32(smem);
    const int l = tid & 31, w = tid >> 5;
    const int m0 = (w & 7) * 32;
    const int n0 = (w >> 3) * (N / 2);
    constexpr int NT = N / 16;   // 8-wide n-tiles per warp

    // ldmatrix per-lane bases (byte addresses)
    const uint32_t aBase = sb + HI_A + (uint32_t)(m0 + (l & 15)) * 272 + ((l >> 4) << 4);
    const uint32_t bBase = sb + HI_B + (uint32_t)(n0 + (l & 7) + ((l >> 4) << 3)) * 272
                         + ((l & 8) << 1);

    float acc[2][NT][4];
    #pragma unroll
    for (int mi = 0; mi < 2; mi++)
        #pragma unroll
        for (int j = 0; j < NT; j++)
            #pragma unroll
            for (int c = 0; c < 4; c++) acc[mi][j][c] = 0.f;

    #pragma unroll
    for (int pass = 0; pass < 3; pass++) {
        const uint32_t aOff = (pass == 2) ? (uint32_t)(LO_A - HI_A) : 0u;
        const uint32_t bOff = (pass == 1) ? (uint32_t)(LO_B - HI_B) : 0u;
        #pragma unroll
        for (int ks = 0; ks < 8; ks++) {
            uint32_t a[2][4], b[NT][2];
            ldm_x4(a[0], aBase + aOff + ks * 32);
            ldm_x4(a[1], aBase + aOff + 16 * 272 + ks * 32);
            #pragma unroll
            for (int j = 0; j < NT / 2; j++) {
                uint32_t r[4];
                ldm_x4(r, bBase + bOff + j * 16 * 272 + ks * 32);
                b[j*2][0] = r[0]; b[j*2][1] = r[1];
                b[j*2+1][0] = r[2]; b[j*2+1][1] = r[3];
            }
            #pragma unroll
            for (int mi = 0; mi < 2; mi++)
                #pragma unroll
                for (int j = 0; j < NT; j++)
                    mma_bf16(acc[mi][j], a[mi], b[j]);
        }
    }

    // ---- epilogue ----
    const int rl = l >> 2;
    const int nc = (l & 3) * 2;
    #pragma unroll
    for (int mi = 0; mi < 2; mi++) {
        const int grow0 = r0 + m0 + mi * 16 + rl;
        const int grow1 = grow0 + 8;
        #pragma unroll
        for (int j = 0; j < NT; j++) {
            const int n = n0 + j * 8 + nc;
            const float b0 = sBias[n], b1 = sBias[n + 1];
            const float v00 = acc[mi][j][0] + b0, v01 = acc[mi][j][1] + b1;
            const float v10 = acc[mi][j][2] + b0, v11 = acc[mi][j][3] + b1;
            if (OMODE == 0) {
                *(float2*)(outf + (size_t)grow0 * 128 + n) = make_float2(v00, v01);
                *(float2*)(outf + (size_t)grow1 * 128 + n) = make_float2(v10, v11);
            } else if (OMODE == 1) {
                uint32_t h, lo;
                cvt2(v00, v01, h, lo);
                *(uint32_t*)(outh + (size_t)grow0 * 128 + n) = h;
                *(uint32_t*)(outl + (size_t)grow0 * 128 + n) = lo;
                cvt2(v10, v11, h, lo);
                *(uint32_t*)(outh + (size_t)grow1 * 128 + n) = h;
                *(uint32_t*)(outl + (size_t)grow1 * 128 + n) = lo;
            } else if (OMODE == 2) {
                const int mh = n >> 4, c = n & 15;
                const int b_ = grow0 >> hwshift;
                const int p0 = grow0 & ((1 << hwshift) - 1);
                const int p1 = grow1 & ((1 << hwshift) - 1);
                float* o0 = outf + ((((size_t)(b_ * 8 + mh) << hwshift) + p0) << 4) + c;
                float* o1 = outf + ((((size_t)(b_ * 8 + mh) << hwshift) + p1) << 4) + c;
                *(float2*)o0 = make_float2(v00, v01);
                *(float2*)o1 = make_float2(v10, v11);
            } else {
                // softmax over the 8-wide n-tile (one group), rows low/high separately
                float mx = fmaxf(v00, v01);
                mx = fmaxf(mx, __shfl_xor_sync(0xffffffffu, mx, 1));
                mx = fmaxf(mx, __shfl_xor_sync(0xffffffffu, mx, 2));
                float e0 = expf(v00 - mx), e1 = expf(v01 - mx);
                float s = e0 + e1;
                s += __shfl_xor_sync(0xffffffffu, s, 1);
                s += __shfl_xor_sync(0xffffffffu, s, 2);
                float inv = 1.f / s;
                *(float2*)(outf + (size_t)grow0 * 64 + n) = make_float2(e0 * inv, e1 * inv);

                float mx2 = fmaxf(v10, v11);
                mx2 = fmaxf(mx2, __shfl_xor_sync(0xffffffffu, mx2, 1));
                mx2 = fmaxf(mx2, __shfl_xor_sync(0xffffffffu, mx2, 2));
                float f0 = expf(v10 - mx2), f1 = expf(v11 - mx2);
                float s2 = f0 + f1;
                s2 += __shfl_xor_sync(0xffffffffu, s2, 1);
                s2 += __shfl_xor_sync(0xffffffffu, s2, 2);
                float inv2 = 1.f / s2;
                *(float2*)(outf + (size_t)grow1 * 64 + n) = make_float2(f0 * inv2, f1 * inv2);
            }
        }
    }
}

// =================================================================================
// Sampler (round-3 proven version): 4 lanes per location, both levels per thread.
// =================================================================================
__global__ void __launch_bounds__(256) k_sample(const float* __restrict__ p_q)
{
    const int t    = blockIdx.x * 256 + threadIdx.x;
    const int lane = t & 3;
    const int loc  = t >> 2;
    const int hb = loc & 3;
    const int qp = (loc >> 2) & 16383;
    const int n  = loc >> 16;
    const int b = n >> 3, m = n & 7;
    const int ks = qp >> 12;
    const int ws = (qp >> 5) & 127;
    const int hs = ((qp & 31) << 2) + hb;

    const float4 Aw = *(const float4*)(g_A + (b * 16384 + qp) * 64 + m * 8 + ((lane & 1) << 2));

    const float* dptr = g_deltas + (b * 16384 + hs * 128 + ws) * 128 + m * 16 + ks * 2;
    const float2 d0 = *(const float2*)dptr;
    const float2 d1 = *(const float2*)(dptr + 8);
    const float2 pq = *(const float2*)(p_q + ((m & 1) * 16384 + hs * 128 + ws) * 2);

    float res[4];
    #pragma unroll
    for (int l = 0; l < 2; l++) {
        const int wl = l ? 128 : 64;
        const float sc = l ? 127.f : 63.f;
        const float mult = (float)wl / sc;
        const float* img = (l ? g_wx1 : g_wx0) + n * (wl * wl * 16) + lane * 4;
        const float2 dxy = l ? d1 : d0;

        const float ix = fmaf(fmaf(pq.x, sc, dxy.x), mult, -0.5f);
        const float iy = fmaf(fmaf(pq.y, sc, dxy.y), mult, -0.5f);
        const float xf = floorf(ix), yf = floorf(iy);
        const float fx1 = ix - xf, fy1 = iy - yf;
        const float fx0 = 1.f - fx1, fy0 = 1.f - fy1;
        const int x0 = (int)xf, y0 = (int)yf;

        float a0 = 0.f, a1 = 0.f, a2 = 0.f, a3 = 0.f;
        #pragma unroll
        for (int tap = 0; tap < 4; tap++) {
            const int xi = x0 + (tap & 1);
            const int yi = y0 + (tap >> 1);
            const float w = ((tap & 1) ? fx1 : fx0) * ((tap >> 1) ? fy1 : fy0);
            if (xi >= 0 && xi < wl && yi >= 0 && yi < wl) {
                float4 v = *(const float4*)(img + ((yi * wl + xi) << 4));
                a0 = fmaf(w, v.x, a0);
                a1 = fmaf(w, v.y, a1);
                a2 = fmaf(w, v.z, a2);
                a3 = fmaf(w, v.w, a3);
            }
        }
        float p = Aw.x * a0 + Aw.y * a1 + Aw.z * a2 + Aw.w * a3;
        float s1 = p + __shfl_xor_sync(0xffffffffu, p, 1);
        float s2 = __shfl_xor_sync(0xffffffffu, s1, 2);
        res[l * 2]     = s1;
        res[l * 2 + 1] = s2;
    }
    if (lane == 0) {
        *(float4*)(g_pre + (size_t)(b * 16384 + qp) * 128 + m * 16 + hb * 4)
            = make_float4(res[0], res[1], res[2], res[3]);
    }
}

// =================================================================================
extern "C" void kernel_launch(void* const* d_in, const int* in_sizes, int n_in,
                              void* d_out, int out_size)
{
    const float* z_q = (const float*)d_in[0];
    const float* x0  = (const float*)d_in[1];
    const float* x1  = (const float*)d_in[2];
    const float* p_q = (const float*)d_in[3];
    const float* Wq  = (const float*)d_in[4];
    const float* bq  = (const float*)d_in[5];
    const float* Wd  = (const float*)d_in[6];
    const float* bd  = (const float*)d_in[7];
    const float* Wa  = (const float*)d_in[8];
    const float* ba  = (const float*)d_in[9];
    const float* Wp  = (const float*)d_in[10];
    const float* bp  = (const float*)d_in[11];
    const float* Wm  = (const float*)d_in[12];
    const float* bm  = (const float*)d_in[13];
    float* out = (float*)d_out;

    const int SM128 = 2 * 256 * 272 + 2 * 128 * 272 + 512;   // 209408
    const int SM64  = 2 * 256 * 272 + 2 * 64 * 272 + 256;    // 174336

    cudaFuncSetAttribute(k_mma<128,0,1>, cudaFuncAttributeMaxDynamicSharedMemorySize, SM128);
    cudaFuncSetAttribute(k_mma<128,1,0>, cudaFuncAttributeMaxDynamicSharedMemorySize, SM128);
    cudaFuncSetAttribute(k_mma<64,1,3>,  cudaFuncAttributeMaxDynamicSharedMemorySize, SM64);
    cudaFuncSetAttribute(k_mma<128,0,2>, cudaFuncAttributeMaxDynamicSharedMemorySize, SM128);
    cudaFuncSetAttribute(k_mma<128,0,0>, cudaFuncAttributeMaxDynamicSharedMemorySize, SM128);

    float *p_deltas, *p_A, *p_wx0, *p_wx1, *p_pre;
    __nv_bfloat16 *zqh, *zql, *wqh, *wql, *wdh, *wdl, *wah, *wal, *wph, *wpl, *wmh, *wml;
    cudaGetSymbolAddress((void**)&p_deltas, g_deltas);
    cudaGetSymbolAddress((void**)&p_A, g_A);
    cudaGetSymbolAddress((void**)&p_wx0, g_wx0);
    cudaGetSymbolAddress((void**)&p_wx1, g_wx1);
    cudaGetSymbolAddress((void**)&p_pre, g_pre);
    cudaGetSymbolAddress((void**)&zqh, g_zq_hi);
    cudaGetSymbolAddress((void**)&zql, g_zq_lo);
    cudaGetSymbolAddress((void**)&wqh, g_Wq_hi);
    cudaGetSymbolAddress((void**)&wql, g_Wq_lo);
    cudaGetSymbolAddress((void**)&wdh, g_Wd_hi);
    cudaGetSymbolAddress((void**)&wdl, g_Wd_lo);
    cudaGetSymbolAddress((void**)&wah, g_Wa_hi);
    cudaGetSymbolAddress((void**)&wal, g_Wa_lo);
    cudaGetSymbolAddress((void**)&wph, g_Wp_hi);
    cudaGetSymbolAddress((void**)&wpl, g_Wp_lo);
    cudaGetSymbolAddress((void**)&wmh, g_Wm_hi);
    cudaGetSymbolAddress((void**)&wml, g_Wm_lo);

    k_prep<<<288, 256>>>(Wq, Wd, Wa, Wp, Wm);
    // zq = z @ Wq + bq -> bf16 hi/lo planes
    k_mma<128,0,1><<<128, 512, SM128>>>(z_q, nullptr, nullptr, wqh, wql, bq,
                                        nullptr, zqh, zql, 0);
    // deltas = zq @ Wd + bd
    k_mma<128,1,0><<<128, 512, SM128>>>(nullptr, zqh, zql, wdh, wdl, bd,
                                        p_deltas, nullptr, nullptr, 0);
    // A = softmax(zq @ Wa + ba)
    k_mma<64,1,3><<<128, 512, SM64>>>(nullptr, zqh, zql, wah, wal, ba,
                                      p_A, nullptr, nullptr, 0);
    // projections (permuted [b,m,y,x,c] layout)
    k_mma<128,0,2><<<32, 512, SM128>>>(x0, nullptr, nullptr, wph, wpl, bp,
                                       p_wx0, nullptr, nullptr, 12);
    k_mma<128,0,2><<<128, 512, SM128>>>(x1, nullptr, nullptr, wph, wpl, bp,
                                        p_wx1, nullptr, nullptr, 14);
    // sampling + attention dot
    k_sample<<<16384, 256>>>(p_q);
    // out = pre @ Wm + bm
    k_mma<128,0,0><<<128, 512, SM128>>>(p_pre, nullptr, nullptr, wmh, wml, bm,
                                        out, nullptr, nullptr, 0);
}